// round 1
// baseline (speedup 1.0000x reference)
#include <cuda_runtime.h>
#include <cuda_bf16.h>

#define BATCH 4
#define NPTS  16384
#define MCTR  4096
#define KNB   32
#define R2    0.01f
#define CH    6   // 3 absolute + 3 relative

// Scratch (allocation-guard-safe __device__ globals)
__device__ float4 g_pts4[BATCH * NPTS];          // (x, y, z, |p|^2)  1 MB
__device__ int    g_idx[BATCH * MCTR * KNB];     // ball-query indices 2 MB

// ---------------------------------------------------------------------------
// Kernel 1: pack planar (3,N) points into float4 AoS with precomputed |p|^2
// ---------------------------------------------------------------------------
__global__ __launch_bounds__(256) void pack_kernel(const float* __restrict__ pts) {
    int t = blockIdx.x * blockDim.x + threadIdx.x;
    if (t >= BATCH * NPTS) return;
    int b = t / NPTS, n = t - b * NPTS;
    const float* p = pts + (size_t)b * 3 * NPTS;
    float x = p[n], y = p[NPTS + n], z = p[2 * NPTS + n];
    // fma-chain, ascending coordinate order (matches gemm-style contraction)
    float p2 = __fmaf_rn(z, z, __fmaf_rn(y, y, __fmul_rn(x, x)));
    g_pts4[t] = make_float4(x, y, z, p2);
}

// ---------------------------------------------------------------------------
// Kernel 2: warp-per-center ball query, ordered slot assignment, early exit
// ---------------------------------------------------------------------------
__global__ __launch_bounds__(256) void ballquery_kernel(const float* __restrict__ centers) {
    int gw   = (blockIdx.x * blockDim.x + threadIdx.x) >> 5;
    int lane = threadIdx.x & 31;
    if (gw >= BATCH * MCTR) return;
    int b = gw / MCTR, m = gw - b * MCTR;

    const float* c = centers + (size_t)b * 3 * MCTR;
    float cx = c[m], cy = c[MCTR + m], cz = c[2 * MCTR + m];
    float c2 = __fmaf_rn(cz, cz, __fmaf_rn(cy, cy, __fmul_rn(cx, cx)));

    const float4* __restrict__ pts = g_pts4 + (size_t)b * NPTS;
    int* __restrict__ out = g_idx + (size_t)gw * KNB;

    unsigned below = (1u << lane) - 1u;
    unsigned cnt = 0;

    #pragma unroll 1
    for (int base = 0; base < NPTS; base += 64) {
        float4 p0 = pts[base + lane];
        float4 p1 = pts[base + 32 + lane];

        // cp = fma-chain ascending k; d2 = (c2 + p2) - 2*cp  (matches reference)
        float cp0 = __fmaf_rn(cz, p0.z, __fmaf_rn(cy, p0.y, __fmul_rn(cx, p0.x)));
        float d20 = __fsub_rn(__fadd_rn(c2, p0.w), __fmul_rn(2.0f, cp0));
        float cp1 = __fmaf_rn(cz, p1.z, __fmaf_rn(cy, p1.y, __fmul_rn(cx, p1.x)));
        float d21 = __fsub_rn(__fadd_rn(c2, p1.w), __fmul_rn(2.0f, cp1));

        unsigned m0 = __ballot_sync(0xffffffffu, d20 < R2);
        unsigned m1 = __ballot_sync(0xffffffffu, d21 < R2);

        unsigned s0 = cnt + __popc(m0 & below);
        if (((m0 >> lane) & 1u) && s0 < KNB) out[s0] = base + lane;
        unsigned cmid = cnt + __popc(m0);

        unsigned s1 = cmid + __popc(m1 & below);
        if (((m1 >> lane) & 1u) && s1 < KNB) out[s1] = base + 32 + lane;
        cnt = cmid + __popc(m1);

        if (cnt >= KNB) break;   // uniform across warp (cnt from ballots)
    }

    if (cnt > KNB) cnt = KNB;
    // pad remaining slots with index 0 (reference zero-pads)
    for (int s = cnt + lane; s < KNB; s += 32) out[s] = 0;
}

// ---------------------------------------------------------------------------
// Kernel 3: tiled gather — 32 centers per block, fully coalesced output writes
// out[b][c*K + k][m], layout (B, 192, M)
// ---------------------------------------------------------------------------
__global__ __launch_bounds__(256) void gather_kernel(const float* __restrict__ centers,
                                                     float* __restrict__ out) {
    __shared__ int   idx_s[32][33];   // padded: conflict-free idx_s[lane][k]
    __shared__ float cs[3][32];

    int b  = blockIdx.y;
    int m0 = blockIdx.x * 32;
    int tid = threadIdx.x;

    // load 32x32 index tile (coalesced: k fastest)
    for (int t = tid; t < 32 * 32; t += 256) {
        int ml = t >> 5, k = t & 31;
        idx_s[ml][k] = g_idx[((size_t)(b * MCTR + m0 + ml)) * KNB + k];
    }
    // load center coords for this tile
    if (tid < 96) {
        int coord = tid / 32, ml = tid - coord * 32;
        cs[coord][ml] = centers[(size_t)b * 3 * MCTR + coord * MCTR + m0 + ml];
    }
    __syncthreads();

    int w = tid >> 5, lane = tid & 31;   // lane indexes m within the tile
    const float4* __restrict__ pts = g_pts4 + (size_t)b * NPTS;
    float cx = cs[0][lane], cy = cs[1][lane], cz = cs[2][lane];

    float* ob = out + (size_t)b * (CH * KNB) * MCTR + m0 + lane;

    #pragma unroll
    for (int j = 0; j < 4; j++) {
        int k = w + j * 8;               // 8 warps cover k = 0..31
        int n = idx_s[lane][k];
        float4 p = pts[n];
        float* o = ob + (size_t)k * MCTR;
        o[(size_t)0 * KNB * MCTR] = p.x;
        o[(size_t)1 * KNB * MCTR] = p.y;
        o[(size_t)2 * KNB * MCTR] = p.z;
        o[(size_t)3 * KNB * MCTR] = __fsub_rn(p.x, cx);
        o[(size_t)4 * KNB * MCTR] = __fsub_rn(p.y, cy);
        o[(size_t)5 * KNB * MCTR] = __fsub_rn(p.z, cz);
    }
}

// ---------------------------------------------------------------------------
extern "C" void kernel_launch(void* const* d_in, const int* in_sizes, int n_in,
                              void* d_out, int out_size) {
    const float* pts = (const float*)d_in[0];
    const float* ctr = (const float*)d_in[1];
    // defensive: points (196608 elems) is the larger input
    if (n_in >= 2 && in_sizes[0] < in_sizes[1]) {
        const float* t = pts; pts = ctr; ctr = t;
    }
    float* out = (float*)d_out;

    pack_kernel<<<(BATCH * NPTS + 255) / 256, 256>>>(pts);
    ballquery_kernel<<<(BATCH * MCTR) / 8, 256>>>(ctr);
    dim3 ggrid(MCTR / 32, BATCH);
    gather_kernel<<<ggrid, 256>>>(ctr, out);
}

// round 2
// speedup vs baseline: 2.4389x; 2.4389x over previous
#include <cuda_runtime.h>
#include <cuda_bf16.h>

#define BATCH 4
#define NPTS  16384
#define MCTR  4096
#define KNB   32
#define R2    0.01f
#define RMARG 0.1005f
#define CH    6
#define NCELL 1000          // 10x10x10 per batch
#define TCELL 4096          // padded (4*1000 -> 4096)
#define CAP   128           // max in-ball candidates kept per center

// Scratch (__device__ globals: allocation-guard-safe)
__device__ float4 g_pts4 [BATCH * NPTS];     // orig order (x,y,z,p2) for gather
__device__ float4 g_spts4[BATCH * NPTS];     // cell-sorted (x,y,z,bitcast idx)
__device__ int    g_cell [BATCH * NPTS];
__device__ int    g_cnt  [TCELL];
__device__ int    g_off  [TCELL + 1];
__device__ int    g_cur  [TCELL];
__device__ int    g_idx  [BATCH * MCTR * KNB];

// ---------------------------------------------------------------------------
__global__ __launch_bounds__(256) void zero_kernel() {
    int t = blockIdx.x * blockDim.x + threadIdx.x;
    if (t < TCELL) g_cnt[t] = 0;
}

// pack planar points -> float4, compute cell id, count per cell
__global__ __launch_bounds__(256) void pack_count_kernel(const float* __restrict__ pts) {
    int t = blockIdx.x * blockDim.x + threadIdx.x;
    if (t >= BATCH * NPTS) return;
    int b = t / NPTS, n = t - b * NPTS;
    const float* p = pts + (size_t)b * 3 * NPTS;
    float x = p[n], y = p[NPTS + n], z = p[2 * NPTS + n];
    float p2 = __fmaf_rn(z, z, __fmaf_rn(y, y, __fmul_rn(x, x)));
    g_pts4[t] = make_float4(x, y, z, p2);
    int ci = min(9, max(0, (int)(x * 10.0f)));
    int cj = min(9, max(0, (int)(y * 10.0f)));
    int ck = min(9, max(0, (int)(z * 10.0f)));
    int gc = b * NCELL + (ci * 10 + cj) * 10 + ck;
    g_cell[t] = gc;
    atomicAdd(&g_cnt[gc], 1);
}

// exclusive scan over 4096 cell counts (single block)
__global__ __launch_bounds__(1024) void scan_kernel() {
    __shared__ int s[1024];
    int tid = threadIdx.x;
    int i0 = tid * 4;
    int v0 = g_cnt[i0], v1 = g_cnt[i0 + 1], v2 = g_cnt[i0 + 2], v3 = g_cnt[i0 + 3];
    int local = v0 + v1 + v2 + v3;
    s[tid] = local;
    __syncthreads();
    for (int off = 1; off < 1024; off <<= 1) {
        int t = (tid >= off) ? s[tid - off] : 0;
        __syncthreads();
        s[tid] += t;
        __syncthreads();
    }
    int excl = s[tid] - local;
    g_off[i0] = excl;           g_cur[i0] = excl;
    g_off[i0 + 1] = excl + v0;  g_cur[i0 + 1] = excl + v0;
    g_off[i0 + 2] = excl + v0 + v1;       g_cur[i0 + 2] = excl + v0 + v1;
    g_off[i0 + 3] = excl + v0 + v1 + v2;  g_cur[i0 + 3] = excl + v0 + v1 + v2;
    if (tid == 1023) g_off[TCELL] = excl + local;  // sentinel = total
}

// scatter points into cell-sorted order; pack orig index into .w
__global__ __launch_bounds__(256) void scatter_kernel() {
    int t = blockIdx.x * blockDim.x + threadIdx.x;
    if (t >= BATCH * NPTS) return;
    int b = t / NPTS, n = t - b * NPTS;
    int gc = g_cell[t];
    int pos = atomicAdd(&g_cur[gc], 1);
    float4 p = g_pts4[t];
    g_spts4[pos] = make_float4(p.x, p.y, p.z, __int_as_float(n));
    (void)b;
}

// ---------------------------------------------------------------------------
// grid-accelerated ball query: warp per center, collect in-ball orig indices,
// bitonic-sort, emit 32 smallest (== first K in index order)
// ---------------------------------------------------------------------------
__global__ __launch_bounds__(256) void query_kernel(const float* __restrict__ centers) {
    __shared__ int lists[8][CAP];
    int gw   = (blockIdx.x * blockDim.x + threadIdx.x) >> 5;
    int wslt = threadIdx.x >> 5;
    int lane = threadIdx.x & 31;
    int b = gw / MCTR, m = gw - b * MCTR;

    const float* c = centers + (size_t)b * 3 * MCTR;
    float cx = c[m], cy = c[MCTR + m], cz = c[2 * MCTR + m];
    float c2 = __fmaf_rn(cz, cz, __fmaf_rn(cy, cy, __fmul_rn(cx, cx)));

    int i0 = max(0, (int)((cx - RMARG) * 10.0f)), i1 = min(9, (int)((cx + RMARG) * 10.0f));
    int j0 = max(0, (int)((cy - RMARG) * 10.0f)), j1 = min(9, (int)((cy + RMARG) * 10.0f));
    int k0 = max(0, (int)((cz - RMARG) * 10.0f)), k1 = min(9, (int)((cz + RMARG) * 10.0f));

    int* lst = lists[wslt];
    unsigned below = (1u << lane) - 1u;
    unsigned cnt = 0;

    for (int ci = i0; ci <= i1; ci++) {
        for (int cj = j0; cj <= j1; cj++) {
            int cb = b * NCELL + (ci * 10 + cj) * 10;       // z-cells contiguous
            int start = g_off[cb + k0];
            int end   = g_off[cb + k1 + 1];
            for (int pb = start; pb < end; pb += 32) {
                int p = pb + lane;
                bool hit = false; int idxv = 0;
                if (p < end) {
                    float4 q = g_spts4[p];
                    float p2 = __fmaf_rn(q.z, q.z, __fmaf_rn(q.y, q.y, __fmul_rn(q.x, q.x)));
                    float cp = __fmaf_rn(cz, q.z, __fmaf_rn(cy, q.y, __fmul_rn(cx, q.x)));
                    float d2 = __fsub_rn(__fadd_rn(c2, p2), __fmul_rn(2.0f, cp));
                    hit = d2 < R2;
                    idxv = __float_as_int(q.w);
                }
                unsigned msk = __ballot_sync(0xffffffffu, hit);
                unsigned pos = cnt + __popc(msk & below);
                if (hit && pos < CAP) lst[pos] = idxv;
                cnt += __popc(msk);
            }
        }
    }

    int eff = min((int)cnt, CAP);
    for (int t = eff + lane; t < CAP; t += 32) lst[t] = 0x7fffffff;
    __syncwarp();

    // bitonic sort CAP=128 elements (ascending)
    #pragma unroll
    for (int k2 = 2; k2 <= CAP; k2 <<= 1) {
        #pragma unroll
        for (int j = k2 >> 1; j > 0; j >>= 1) {
            #pragma unroll
            for (int t = 0; t < CAP / 32; t++) {
                int i = lane + t * 32;
                int ixj = i ^ j;
                if (ixj > i) {
                    int a = lst[i], bb = lst[ixj];
                    bool up = ((i & k2) == 0);
                    if ((a > bb) == up) { lst[i] = bb; lst[ixj] = a; }
                }
            }
            __syncwarp();
        }
    }

    int v = lst[lane];
    g_idx[(size_t)gw * KNB + lane] = (lane < eff) ? v : 0;
}

// ---------------------------------------------------------------------------
// tiled gather: 32 centers/block, coalesced writes along m
// ---------------------------------------------------------------------------
__global__ __launch_bounds__(256) void gather_kernel(const float* __restrict__ centers,
                                                     float* __restrict__ out) {
    __shared__ int   idx_s[32][33];
    __shared__ float cs[3][32];

    int b  = blockIdx.y;
    int m0 = blockIdx.x * 32;
    int tid = threadIdx.x;

    for (int t = tid; t < 32 * 32; t += 256) {
        int ml = t >> 5, k = t & 31;
        idx_s[ml][k] = g_idx[((size_t)(b * MCTR + m0 + ml)) * KNB + k];
    }
    if (tid < 96) {
        int coord = tid / 32, ml = tid - coord * 32;
        cs[coord][ml] = centers[(size_t)b * 3 * MCTR + coord * MCTR + m0 + ml];
    }
    __syncthreads();

    int w = tid >> 5, lane = tid & 31;
    const float4* __restrict__ pts = g_pts4 + (size_t)b * NPTS;
    float cx = cs[0][lane], cy = cs[1][lane], cz = cs[2][lane];

    float* ob = out + (size_t)b * (CH * KNB) * MCTR + m0 + lane;

    #pragma unroll
    for (int j = 0; j < 4; j++) {
        int k = w + j * 8;
        int n = idx_s[lane][k];
        float4 p = pts[n];
        float* o = ob + (size_t)k * MCTR;
        o[(size_t)0 * KNB * MCTR] = p.x;
        o[(size_t)1 * KNB * MCTR] = p.y;
        o[(size_t)2 * KNB * MCTR] = p.z;
        o[(size_t)3 * KNB * MCTR] = __fsub_rn(p.x, cx);
        o[(size_t)4 * KNB * MCTR] = __fsub_rn(p.y, cy);
        o[(size_t)5 * KNB * MCTR] = __fsub_rn(p.z, cz);
    }
}

// ---------------------------------------------------------------------------
extern "C" void kernel_launch(void* const* d_in, const int* in_sizes, int n_in,
                              void* d_out, int out_size) {
    const float* pts = (const float*)d_in[0];
    const float* ctr = (const float*)d_in[1];
    if (n_in >= 2 && in_sizes[0] < in_sizes[1]) {
        const float* t = pts; pts = ctr; ctr = t;
    }
    float* out = (float*)d_out;

    zero_kernel<<<TCELL / 256, 256>>>();
    pack_count_kernel<<<(BATCH * NPTS) / 256, 256>>>(pts);
    scan_kernel<<<1, 1024>>>();
    scatter_kernel<<<(BATCH * NPTS) / 256, 256>>>();
    query_kernel<<<(BATCH * MCTR) / 8, 256>>>(ctr);
    dim3 ggrid(MCTR / 32, BATCH);
    gather_kernel<<<ggrid, 256>>>(ctr, out);
}